// round 12
// baseline (speedup 1.0000x reference)
#include <cuda_runtime.h>
#include <cuda_bf16.h>
#include <math.h>
#include <stdint.h>

#define T_LEN   512
#define B_SZ    128
#define H_SZ    1024
#define NIN     128
#define NOUT    128
#define ALPHA_F 0.25f
#define LEAK_F  0.75f
#define NSCALE  0.025f
#define GRID_RNN 128
#define BH      (B_SZ * H_SZ)

// rnn SMEM (bytes): A tile 64 rows x 528B pitch hi+lo; B tile 64 x 528 hi+lo
#define PITCH  528
#define A_HI   0
#define A_LO   33792
#define B_HI   67584
#define B_LO   101376
#define SM_ALLOC 135168

// tensorized pre/post kernels SMEM
#define P_AH   0
#define P_AL   67584
#define P_BH   135168
#define P_BL   168960
#define P_SMEM 202752

// ---------------- device scratch ----------------
__device__ float g_c[(size_t)T_LEN * BH];
__device__ __nv_bfloat16 g_a_hi[BH];
__device__ __nv_bfloat16 g_a_lo[BH];
__device__ float g_p[4 * BH];                    // 4 split-K partials
__device__ unsigned g_bar_count;
__device__ unsigned g_rel[GRID_RNN * 32];

__device__ __forceinline__ void mma_bf16(float& c0, float& c1, float& c2, float& c3,
                                         uint32_t a0, uint32_t a1, uint32_t a2, uint32_t a3,
                                         uint32_t b0, uint32_t b1) {
    asm volatile(
        "mma.sync.aligned.m16n8k16.row.col.f32.bf16.bf16.f32 "
        "{%0,%1,%2,%3}, {%4,%5,%6,%7}, {%8,%9}, {%0,%1,%2,%3};"
        : "+f"(c0), "+f"(c1), "+f"(c2), "+f"(c3)
        : "r"(a0), "r"(a1), "r"(a2), "r"(a3), "r"(b0), "r"(b1));
}

__device__ __forceinline__ uint32_t pack_bf16(float a, float b) {
    __nv_bfloat16 x = __float2bfloat16(a), y = __float2bfloat16(b);
    return (uint32_t)__bfloat16_as_ushort(x) | ((uint32_t)__bfloat16_as_ushort(y) << 16);
}

// ---------------- init ----------------
__global__ void init_kernel(const float* __restrict__ hidden) {
    int i = blockIdx.x * blockDim.x + threadIdx.x;
    if (i == 0) g_bar_count = 0u;
    if (i < GRID_RNN * 32) g_rel[i] = 0u;
    if (i < BH) {
        float t = tanhf(hidden[i]);
        __nv_bfloat16 hi = __float2bfloat16(t);
        g_a_hi[i] = hi;
        g_a_lo[i] = __float2bfloat16(t - __bfloat162float(hi));
    }
}

// ------- pre (tensor cores): c = alpha*(x@Win^T + b_in + b_hh) + 0.025*noise
__global__ void __launch_bounds__(256, 1) pre_tc_kernel(
    const float* __restrict__ x, const float* __restrict__ noise,
    const float* __restrict__ w_in, const float* __restrict__ b_in,
    const float* __restrict__ b_hh)
{
    extern __shared__ char sm[];
    const int tid = threadIdx.x;
    const int c0 = blockIdx.x * 64;
    const int r0 = blockIdx.y * 128;
    const int wid = tid >> 5, lane = tid & 31;
    const int wm = (wid & 3) * 32;
    const int wn = (wid >> 2) * 32;
    const int gq = lane >> 2, q = lane & 3;

    float acc[2][4][4] = {};

    const char* pAh = sm + P_AH + (wm + gq) * PITCH + q * 4;
    const char* pAl = sm + P_AL + (wm + gq) * PITCH + q * 4;
    const char* pBh = sm + P_BH + (wn + gq) * PITCH + q * 4;
    const char* pBl = sm + P_BL + (wn + gq) * PITCH + q * 4;

    #pragma unroll
    for (int ch = 0; ch < 2; ch++) {
        const int kc = ch * 64;
        __syncthreads();
        #pragma unroll
        for (int i = 0; i < 8; i++) {
            int idx = i * 256 + tid;
            int r = idx >> 4, c4 = idx & 15;
            int rr = r0 + r;
            const float* src = x + ((size_t)(rr & 127) * T_LEN + (rr >> 7)) * NIN + kc + c4 * 4;
            float4 v = __ldcg((const float4*)src);
            float hx = __bfloat162float(__float2bfloat16(v.x));
            float hy = __bfloat162float(__float2bfloat16(v.y));
            float hz = __bfloat162float(__float2bfloat16(v.z));
            float hw = __bfloat162float(__float2bfloat16(v.w));
            *(uint2*)(sm + P_AH + r * PITCH + c4 * 8) =
                make_uint2(pack_bf16(v.x, v.y), pack_bf16(v.z, v.w));
            *(uint2*)(sm + P_AL + r * PITCH + c4 * 8) =
                make_uint2(pack_bf16(v.x - hx, v.y - hy), pack_bf16(v.z - hz, v.w - hw));
        }
        #pragma unroll
        for (int i = 0; i < 4; i++) {
            int idx = i * 256 + tid;
            int r = idx >> 4, c4 = idx & 15;
            float4 v = __ldcg((const float4*)(w_in + (size_t)(c0 + r) * NIN + kc + c4 * 4));
            float hx = __bfloat162float(__float2bfloat16(v.x));
            float hy = __bfloat162float(__float2bfloat16(v.y));
            float hz = __bfloat162float(__float2bfloat16(v.z));
            float hw = __bfloat162float(__float2bfloat16(v.w));
            *(uint2*)(sm + P_BH + r * PITCH + c4 * 8) =
                make_uint2(pack_bf16(v.x, v.y), pack_bf16(v.z, v.w));
            *(uint2*)(sm + P_BL + r * PITCH + c4 * 8) =
                make_uint2(pack_bf16(v.x - hx, v.y - hy), pack_bf16(v.z - hz, v.w - hw));
        }
        __syncthreads();

        #pragma unroll
        for (int kk = 0; kk < 4; kk++) {
            const int kb = kk * 32;
            uint32_t ah[2][4], al[2][4], bhf[4][2], blf[4][2];
            #pragma unroll
            for (int mt = 0; mt < 2; mt++) {
                const int mo = mt * 16 * PITCH;
                ah[mt][0] = *(const uint32_t*)(pAh + mo + kb);
                ah[mt][1] = *(const uint32_t*)(pAh + mo + 8 * PITCH + kb);
                ah[mt][2] = *(const uint32_t*)(pAh + mo + kb + 16);
                ah[mt][3] = *(const uint32_t*)(pAh + mo + 8 * PITCH + kb + 16);
                al[mt][0] = *(const uint32_t*)(pAl + mo + kb);
                al[mt][1] = *(const uint32_t*)(pAl + mo + 8 * PITCH + kb);
                al[mt][2] = *(const uint32_t*)(pAl + mo + kb + 16);
                al[mt][3] = *(const uint32_t*)(pAl + mo + 8 * PITCH + kb + 16);
            }
            #pragma unroll
            for (int j = 0; j < 4; j++) {
                bhf[j][0] = *(const uint32_t*)(pBh + j * 8 * PITCH + kb);
                bhf[j][1] = *(const uint32_t*)(pBh + j * 8 * PITCH + kb + 16);
                blf[j][0] = *(const uint32_t*)(pBl + j * 8 * PITCH + kb);
                blf[j][1] = *(const uint32_t*)(pBl + j * 8 * PITCH + kb + 16);
            }
            #pragma unroll
            for (int mt = 0; mt < 2; mt++)
                #pragma unroll
                for (int j = 0; j < 4; j++) {
                    mma_bf16(acc[mt][j][0], acc[mt][j][1], acc[mt][j][2], acc[mt][j][3],
                             ah[mt][0], ah[mt][1], ah[mt][2], ah[mt][3], bhf[j][0], bhf[j][1]);
                    mma_bf16(acc[mt][j][0], acc[mt][j][1], acc[mt][j][2], acc[mt][j][3],
                             ah[mt][0], ah[mt][1], ah[mt][2], ah[mt][3], blf[j][0], blf[j][1]);
                    mma_bf16(acc[mt][j][0], acc[mt][j][1], acc[mt][j][2], acc[mt][j][3],
                             al[mt][0], al[mt][1], al[mt][2], al[mt][3], bhf[j][0], bhf[j][1]);
                }
        }
    }

    #pragma unroll
    for (int j = 0; j < 4; j++) {
        int col = c0 + wn + j * 8 + q * 2;
        float bi0 = b_in[col] + b_hh[col];
        float bi1 = b_in[col + 1] + b_hh[col + 1];
        #pragma unroll
        for (int mt = 0; mt < 2; mt++) {
            int row = r0 + wm + mt * 16 + gq;
            float2 n0 = __ldcg((const float2*)(noise + (size_t)row * H_SZ + col));
            float2 n1 = __ldcg((const float2*)(noise + (size_t)(row + 8) * H_SZ + col));
            float2 v0, v1;
            v0.x = ALPHA_F * (acc[mt][j][0] + bi0) + NSCALE * n0.x;
            v0.y = ALPHA_F * (acc[mt][j][1] + bi1) + NSCALE * n0.y;
            v1.x = ALPHA_F * (acc[mt][j][2] + bi0) + NSCALE * n1.x;
            v1.y = ALPHA_F * (acc[mt][j][3] + bi1) + NSCALE * n1.y;
            *(float2*)(g_c + (size_t)row * H_SZ + col) = v0;
            *(float2*)(g_c + (size_t)(row + 8) * H_SZ + col) = v1;
        }
    }
}

// ---- grid barrier: atomic arrival + per-CTA-line release (proven) ----------
__device__ __forceinline__ void grid_bar(int cta, unsigned epoch, unsigned* smflag) {
    __syncthreads();
    if (threadIdx.x == 0) {
        __threadfence();
        unsigned arrived = atomicAdd(&g_bar_count, 1u) + 1u;
        *smflag = (arrived == epoch * (unsigned)GRID_RNN) ? 1u : 0u;
    }
    __syncthreads();
    if (*smflag) {
        if (threadIdx.x < GRID_RNN) {
            *(volatile unsigned*)&g_rel[threadIdx.x * 32] = epoch;
        }
    } else if (threadIdx.x == 0) {
        while (*(volatile unsigned*)&g_rel[cta * 32] < epoch) { }
        __threadfence();
    }
    __syncthreads();
}

// ---------------- persistent recurrent kernel (R8 + pipelined A staging) ----
// 128 CTAs = 4 k-splits x 2 b-tiles x 16 h-tiles. 256 threads, 8 warps 16x32.
// Per step: stage chunk0 | GEMM0 while chunk1 LDGs in flight | GEMM1.
__global__ void __launch_bounds__(256, 1) rnn_kernel(
    float* __restrict__ hid_list, float* __restrict__ h_final,
    const float* __restrict__ w_hh, const float* __restrict__ hidden0)
{
    extern __shared__ char sm[];
    __shared__ unsigned smflag;
    const int cta = blockIdx.x;
    const int ks = cta & 3;
    const int bt = (cta >> 2) & 1;
    const int ht = cta >> 3;
    const int tid = threadIdx.x;
    const int r0 = bt * 64, c0 = ht * 64, k0 = ks * 256;

    for (int e = tid; e < 64 * 256; e += 256) {
        int n = e >> 8, k = e & 255;
        float w = w_hh[(size_t)(c0 + n) * H_SZ + k0 + k];
        __nv_bfloat16 wh = __float2bfloat16(w);
        __nv_bfloat16 wl = __float2bfloat16(w - __bfloat162float(wh));
        *(__nv_bfloat16*)(sm + B_HI + n * PITCH + k * 2) = wh;
        *(__nv_bfloat16*)(sm + B_LO + n * PITCH + k * 2) = wl;
    }
    __syncthreads();

    const int wid = tid >> 5, lane = tid & 31;
    const int wm = (wid & 3) * 16;
    const int wn = (wid >> 2) * 32;
    const int gq = lane >> 2;
    const int q  = lane & 3;

    float* pout = g_p + (size_t)ks * BH;
    const char* pAh = sm + A_HI + (wm + gq) * PITCH + q * 4;
    const char* pAl = sm + A_LO + (wm + gq) * PITCH + q * 4;
    const char* pBh = sm + B_HI + (wn + gq) * PITCH + q * 4;
    const char* pBl = sm + B_LO + (wn + gq) * PITCH + q * 4;

    const int e  = cta * 1024 + tid * 4;
    const int eb = e >> 10, eh = e & 1023;

    // per-thread staging coords: idx 0..1023 => r 0..63, cc 0..15 (x16B)
    const int sr = tid >> 2;                 // uses i*256+tid below; recompute per i
    (void)sr;

    float4 hreg = *(const float4*)(hidden0 + e);
    unsigned epoch = 0;

    for (int t = 0; t < T_LEN; t++) {
        float4 cv = __ldcg((const float4*)(g_c + (size_t)t * BH + e));

        // ---- stage chunk0 (k bytes 0..255 of the tile) ----
        uint4 vh0[4], vl0[4];
        #pragma unroll
        for (int i = 0; i < 4; i++) {
            int idx = i * 256 + tid;             // 0..1023
            int r = idx >> 4, cc = idx & 15;
            size_t goff = (size_t)(r0 + r) * 2048 + (size_t)k0 * 2 + cc * 16;
            vh0[i] = __ldcg((const uint4*)((const char*)g_a_hi + goff));
            vl0[i] = __ldcg((const uint4*)((const char*)g_a_lo + goff));
        }
        #pragma unroll
        for (int i = 0; i < 4; i++) {
            int idx = i * 256 + tid;
            int r = idx >> 4, cc = idx & 15;
            *(uint4*)(sm + A_HI + r * PITCH + cc * 16) = vh0[i];
            *(uint4*)(sm + A_LO + r * PITCH + cc * 16) = vl0[i];
        }
        __syncthreads();

        // ---- issue chunk1 LDGs (latency hides under GEMM0) ----
        uint4 vh1[4], vl1[4];
        #pragma unroll
        for (int i = 0; i < 4; i++) {
            int idx = i * 256 + tid;
            int r = idx >> 4, cc = idx & 15;
            size_t goff = (size_t)(r0 + r) * 2048 + (size_t)k0 * 2 + 256 + cc * 16;
            vh1[i] = __ldcg((const uint4*)((const char*)g_a_hi + goff));
            vl1[i] = __ldcg((const uint4*)((const char*)g_a_lo + goff));
        }

        float acc[4][4] = {};
        // ---- GEMM0: kk 0..7 (reads tile bytes 0..255 only) ----
        #pragma unroll
        for (int kk = 0; kk < 8; kk++) {
            const int kb = kk * 32;
            uint32_t ah0 = *(const uint32_t*)(pAh + kb);
            uint32_t ah1 = *(const uint32_t*)(pAh + 8 * PITCH + kb);
            uint32_t ah2 = *(const uint32_t*)(pAh + kb + 16);
            uint32_t ah3 = *(const uint32_t*)(pAh + 8 * PITCH + kb + 16);
            uint32_t al0 = *(const uint32_t*)(pAl + kb);
            uint32_t al1 = *(const uint32_t*)(pAl + 8 * PITCH + kb);
            uint32_t al2 = *(const uint32_t*)(pAl + kb + 16);
            uint32_t al3 = *(const uint32_t*)(pAl + 8 * PITCH + kb + 16);
            #pragma unroll
            for (int j = 0; j < 4; j++) {
                uint32_t bh0 = *(const uint32_t*)(pBh + j * 8 * PITCH + kb);
                uint32_t bh1 = *(const uint32_t*)(pBh + j * 8 * PITCH + kb + 16);
                uint32_t bl0 = *(const uint32_t*)(pBl + j * 8 * PITCH + kb);
                uint32_t bl1 = *(const uint32_t*)(pBl + j * 8 * PITCH + kb + 16);
                mma_bf16(acc[j][0], acc[j][1], acc[j][2], acc[j][3],
                         ah0, ah1, ah2, ah3, bh0, bh1);
                mma_bf16(acc[j][0], acc[j][1], acc[j][2], acc[j][3],
                         ah0, ah1, ah2, ah3, bl0, bl1);
                mma_bf16(acc[j][0], acc[j][1], acc[j][2], acc[j][3],
                         al0, al1, al2, al3, bh0, bh1);
            }
        }

        // ---- store chunk1, sync, GEMM1: kk 8..15 ----
        #pragma unroll
        for (int i = 0; i < 4; i++) {
            int idx = i * 256 + tid;
            int r = idx >> 4, cc = idx & 15;
            *(uint4*)(sm + A_HI + r * PITCH + 256 + cc * 16) = vh1[i];
            *(uint4*)(sm + A_LO + r * PITCH + 256 + cc * 16) = vl1[i];
        }
        __syncthreads();

        #pragma unroll
        for (int kk = 8; kk < 16; kk++) {
            const int kb = kk * 32;
            uint32_t ah0 = *(const uint32_t*)(pAh + kb);
            uint32_t ah1 = *(const uint32_t*)(pAh + 8 * PITCH + kb);
            uint32_t ah2 = *(const uint32_t*)(pAh + kb + 16);
            uint32_t ah3 = *(const uint32_t*)(pAh + 8 * PITCH + kb + 16);
            uint32_t al0 = *(const uint32_t*)(pAl + kb);
            uint32_t al1 = *(const uint32_t*)(pAl + 8 * PITCH + kb);
            uint32_t al2 = *(const uint32_t*)(pAl + kb + 16);
            uint32_t al3 = *(const uint32_t*)(pAl + 8 * PITCH + kb + 16);
            #pragma unroll
            for (int j = 0; j < 4; j++) {
                uint32_t bh0 = *(const uint32_t*)(pBh + j * 8 * PITCH + kb);
                uint32_t bh1 = *(const uint32_t*)(pBh + j * 8 * PITCH + kb + 16);
                uint32_t bl0 = *(const uint32_t*)(pBl + j * 8 * PITCH + kb);
                uint32_t bl1 = *(const uint32_t*)(pBl + j * 8 * PITCH + kb + 16);
                mma_bf16(acc[j][0], acc[j][1], acc[j][2], acc[j][3],
                         ah0, ah1, ah2, ah3, bh0, bh1);
                mma_bf16(acc[j][0], acc[j][1], acc[j][2], acc[j][3],
                         ah0, ah1, ah2, ah3, bl0, bl1);
                mma_bf16(acc[j][0], acc[j][1], acc[j][2], acc[j][3],
                         al0, al1, al2, al3, bh0, bh1);
            }
        }

        #pragma unroll
        for (int j = 0; j < 4; j++) {
            float* pp = pout + (size_t)(r0 + wm + gq) * H_SZ + c0 + wn + j * 8 + q * 2;
            *(float2*)pp = make_float2(acc[j][0], acc[j][1]);
            *(float2*)(pp + 8 * H_SZ) = make_float2(acc[j][2], acc[j][3]);
        }

        grid_bar(cta, ++epoch, &smflag);

        {
            float4 p0 = *(const float4*)(g_p + e);
            float4 p1 = *(const float4*)(g_p + 1 * BH + e);
            float4 p2 = *(const float4*)(g_p + 2 * BH + e);
            float4 p3 = *(const float4*)(g_p + 3 * BH + e);
            float4 hn;
            hn.x = LEAK_F * hreg.x + ALPHA_F * (p0.x + p1.x + p2.x + p3.x) + cv.x;
            hn.y = LEAK_F * hreg.y + ALPHA_F * (p0.y + p1.y + p2.y + p3.y) + cv.y;
            hn.z = LEAK_F * hreg.z + ALPHA_F * (p0.z + p1.z + p2.z + p3.z) + cv.z;
            hn.w = LEAK_F * hreg.w + ALPHA_F * (p0.w + p1.w + p2.w + p3.w) + cv.w;
            hreg = hn;
            *(float4*)(hid_list + ((size_t)eb * T_LEN + t) * H_SZ + eh) = hn;
            if (t == T_LEN - 1) *(float4*)(h_final + e) = hn;

            float t0 = tanhf(hn.x), t1 = tanhf(hn.y), t2 = tanhf(hn.z), t3 = tanhf(hn.w);
            __nv_bfloat16 h0 = __float2bfloat16(t0), h1 = __float2bfloat16(t1);
            __nv_bfloat16 h2 = __float2bfloat16(t2), h3 = __float2bfloat16(t3);
            __nv_bfloat16 l0 = __float2bfloat16(t0 - __bfloat162float(h0));
            __nv_bfloat16 l1 = __float2bfloat16(t1 - __bfloat162float(h1));
            __nv_bfloat16 l2 = __float2bfloat16(t2 - __bfloat162float(h2));
            __nv_bfloat16 l3 = __float2bfloat16(t3 - __bfloat162float(h3));
            uint2 hw, lw;
            hw.x = (uint32_t)__bfloat16_as_ushort(h0) | ((uint32_t)__bfloat16_as_ushort(h1) << 16);
            hw.y = (uint32_t)__bfloat16_as_ushort(h2) | ((uint32_t)__bfloat16_as_ushort(h3) << 16);
            lw.x = (uint32_t)__bfloat16_as_ushort(l0) | ((uint32_t)__bfloat16_as_ushort(l1) << 16);
            lw.y = (uint32_t)__bfloat16_as_ushort(l2) | ((uint32_t)__bfloat16_as_ushort(l3) << 16);
            *(uint2*)((char*)g_a_hi + (size_t)e * 2) = hw;
            *(uint2*)((char*)g_a_lo + (size_t)e * 2) = lw;
        }

        grid_bar(cta, ++epoch, &smflag);
    }
}

// ------- post (tensor cores, grid-swapped) -----------------------------------
__global__ void __launch_bounds__(256, 1) post_tc_kernel(
    const float* __restrict__ hid_list, const float* __restrict__ w_out,
    const float* __restrict__ b_out, float* __restrict__ out_list)
{
    extern __shared__ char sm[];
    const int tid = threadIdx.x;
    const int c0 = blockIdx.x * 64;
    const int r0 = blockIdx.y * 128;
    const int wid = tid >> 5, lane = tid & 31;
    const int wm = (wid & 3) * 32;
    const int wn = (wid >> 2) * 32;
    const int gq = lane >> 2, q = lane & 3;

    float acc[2][4][4] = {};

    const char* pAh = sm + P_AH + (wm + gq) * PITCH + q * 4;
    const char* pAl = sm + P_AL + (wm + gq) * PITCH + q * 4;
    const char* pBh = sm + P_BH + (wn + gq) * PITCH + q * 4;
    const char* pBl = sm + P_BL + (wn + gq) * PITCH + q * 4;

    for (int ch = 0; ch < 16; ch++) {
        const int kc = ch * 64;
        __syncthreads();
        #pragma unroll
        for (int i = 0; i < 8; i++) {
            int idx = i * 256 + tid;
            int r = idx >> 4, c4 = idx & 15;
            float4 v = __ldcg((const float4*)(hid_list + (size_t)(r0 + r) * H_SZ + kc + c4 * 4));
            float hx = __bfloat162float(__float2bfloat16(v.x));
            float hy = __bfloat162float(__float2bfloat16(v.y));
            float hz = __bfloat162float(__float2bfloat16(v.z));
            float hw = __bfloat162float(__float2bfloat16(v.w));
            *(uint2*)(sm + P_AH + r * PITCH + c4 * 8) =
                make_uint2(pack_bf16(v.x, v.y), pack_bf16(v.z, v.w));
            *(uint2*)(sm + P_AL + r * PITCH + c4 * 8) =
                make_uint2(pack_bf16(v.x - hx, v.y - hy), pack_bf16(v.z - hz, v.w - hw));
        }
        #pragma unroll
        for (int i = 0; i < 4; i++) {
            int idx = i * 256 + tid;
            int r = idx >> 4, c4 = idx & 15;
            float4 v = __ldcg((const float4*)(w_out + (size_t)(c0 + r) * H_SZ + kc + c4 * 4));
            float hx = __bfloat162float(__float2bfloat16(v.x));
            float hy = __bfloat162float(__float2bfloat16(v.y));
            float hz = __bfloat162float(__float2bfloat16(v.z));
            float hw = __bfloat162float(__float2bfloat16(v.w));
            *(uint2*)(sm + P_BH + r * PITCH + c4 * 8) =
                make_uint2(pack_bf16(v.x, v.y), pack_bf16(v.z, v.w));
            *(uint2*)(sm + P_BL + r * PITCH + c4 * 8) =
                make_uint2(pack_bf16(v.x - hx, v.y - hy), pack_bf16(v.z - hz, v.w - hw));
        }
        __syncthreads();

        #pragma unroll
        for (int kk = 0; kk < 4; kk++) {
            const int kb = kk * 32;
            uint32_t ah[2][4], al[2][4], bhf[4][2], blf[4][2];
            #pragma unroll
            for (int mt = 0; mt < 2; mt++) {
                const int mo = mt * 16 * PITCH;
                ah[mt][0] = *(const uint32_t*)(pAh + mo + kb);
                ah[mt][1] = *(const uint32_t*)(pAh + mo + 8 * PITCH + kb);
                ah[mt][2] = *(const uint32_t*)(pAh + mo + kb + 16);
                ah[mt][3] = *(const uint32_t*)(pAh + mo + 8 * PITCH + kb + 16);
                al[mt][0] = *(const uint32_t*)(pAl + mo + kb);
                al[mt][1] = *(const uint32_t*)(pAl + mo + 8 * PITCH + kb);
                al[mt][2] = *(const uint32_t*)(pAl + mo + kb + 16);
                al[mt][3] = *(const uint32_t*)(pAl + mo + 8 * PITCH + kb + 16);
            }
            #pragma unroll
            for (int j = 0; j < 4; j++) {
                bhf[j][0] = *(const uint32_t*)(pBh + j * 8 * PITCH + kb);
                bhf[j][1] = *(const uint32_t*)(pBh + j * 8 * PITCH + kb + 16);
                blf[j][0] = *(const uint32_t*)(pBl + j * 8 * PITCH + kb);
                blf[j][1] = *(const uint32_t*)(pBl + j * 8 * PITCH + kb + 16);
            }
            #pragma unroll
            for (int mt = 0; mt < 2; mt++)
                #pragma unroll
                for (int j = 0; j < 4; j++) {
                    mma_bf16(acc[mt][j][0], acc[mt][j][1], acc[mt][j][2], acc[mt][j][3],
                             ah[mt][0], ah[mt][1], ah[mt][2], ah[mt][3], bhf[j][0], bhf[j][1]);
                    mma_bf16(acc[mt][j][0], acc[mt][j][1], acc[mt][j][2], acc[mt][j][3],
                             ah[mt][0], ah[mt][1], ah[mt][2], ah[mt][3], blf[j][0], blf[j][1]);
                    mma_bf16(acc[mt][j][0], acc[mt][j][1], acc[mt][j][2], acc[mt][j][3],
                             al[mt][0], al[mt][1], al[mt][2], al[mt][3], bhf[j][0], bhf[j][1]);
                }
        }
    }

    #pragma unroll
    for (int mt = 0; mt < 2; mt++) {
        #pragma unroll
        for (int j = 0; j < 4; j++) {
            int col = c0 + wn + j * 8 + q * 2;
            float b0 = b_out[col], b1 = b_out[col + 1];
            int row = r0 + wm + mt * 16 + gq;
            float2 v0, v1;
            v0.x = fminf(fmaxf(acc[mt][j][0] + b0, -20.0f), 20.0f);
            v0.y = fminf(fmaxf(acc[mt][j][1] + b1, -20.0f), 20.0f);
            v1.x = fminf(fmaxf(acc[mt][j][2] + b0, -20.0f), 20.0f);
            v1.y = fminf(fmaxf(acc[mt][j][3] + b1, -20.0f), 20.0f);
            *(float2*)(out_list + (size_t)row * NOUT + col) = v0;
            *(float2*)(out_list + (size_t)(row + 8) * NOUT + col) = v1;
        }
    }
}

extern "C" void kernel_launch(void* const* d_in, const int* in_sizes, int n_in,
                              void* d_out, int out_size) {
    const float* x       = (const float*)d_in[0];
    const float* hidden0 = (const float*)d_in[1];
    const float* noise   = (const float*)d_in[2];
    const float* w_in_w  = (const float*)d_in[3];
    const float* w_in_b  = (const float*)d_in[4];
    const float* w_hh_w  = (const float*)d_in[5];
    const float* w_hh_b  = (const float*)d_in[6];
    const float* w_out_w = (const float*)d_in[7];
    const float* w_out_b = (const float*)d_in[8];

    float* out      = (float*)d_out;
    float* hid_list = out;
    float* out_list = out + (size_t)B_SZ * T_LEN * H_SZ;
    float* h_final  = out_list + (size_t)B_SZ * T_LEN * NOUT;

    cudaFuncSetAttribute(rnn_kernel, cudaFuncAttributeMaxDynamicSharedMemorySize, SM_ALLOC);
    cudaFuncSetAttribute(pre_tc_kernel, cudaFuncAttributeMaxDynamicSharedMemorySize, P_SMEM);
    cudaFuncSetAttribute(post_tc_kernel, cudaFuncAttributeMaxDynamicSharedMemorySize, P_SMEM);
    init_kernel<<<(BH + 255) / 256, 256>>>(hidden0);
    pre_tc_kernel<<<dim3(H_SZ / 64, (T_LEN * B_SZ) / 128), 256, P_SMEM>>>(
        x, noise, w_in_w, w_in_b, w_hh_b);
    rnn_kernel<<<GRID_RNN, 256, SM_ALLOC>>>(hid_list, h_final, w_hh_w, hidden0);
    post_tc_kernel<<<dim3(NOUT / 64, (B_SZ * T_LEN) / 128), 256, P_SMEM>>>(
        hid_list, w_out_w, w_out_b, out_list);
}

// round 13
// speedup vs baseline: 1.0867x; 1.0867x over previous
#include <cuda_runtime.h>
#include <cuda_fp16.h>
#include <math.h>
#include <stdint.h>

#define T_LEN   512
#define B_SZ    128
#define H_SZ    1024
#define NIN     128
#define NOUT    128
#define ALPHA_F 0.25f
#define LEAK_F  0.75f
#define NSCALE  0.025f
#define GRID_RNN 128
#define BH      (B_SZ * H_SZ)

// rnn SMEM (bytes): A tile 64 x 528 (single fp16); B tile 64 x 528 hi+lo
#define PITCH  528
#define A_SM   0
#define B_HI   33792
#define B_LO   67584
#define SM_ALLOC 101376

// pre/post SMEM: A single (128 x 528), B hi+lo (64 x 528 each)
#define P_A    0
#define P_BH   67584
#define P_BL   101376
#define P_SMEM 135168

// ---------------- device scratch ----------------
__device__ float g_c[(size_t)T_LEN * BH];
__device__ __half g_a[BH];                       // tanh(h) as fp16 (single)
__device__ float g_p[4 * BH];                    // 4 split-K partials
__device__ unsigned g_bar_count;
__device__ unsigned g_rel[GRID_RNN * 32];

// fp16 mma m16n8k16, fp32 accum (baseline PTX, works on compute_103)
__device__ __forceinline__ void mma_f16(float& c0, float& c1, float& c2, float& c3,
                                        uint32_t a0, uint32_t a1, uint32_t a2, uint32_t a3,
                                        uint32_t b0, uint32_t b1) {
    asm volatile(
        "mma.sync.aligned.m16n8k16.row.col.f32.f16.f16.f32 "
        "{%0,%1,%2,%3}, {%4,%5,%6,%7}, {%8,%9}, {%0,%1,%2,%3};"
        : "+f"(c0), "+f"(c1), "+f"(c2), "+f"(c3)
        : "r"(a0), "r"(a1), "r"(a2), "r"(a3), "r"(b0), "r"(b1));
}

__device__ __forceinline__ uint32_t pack_h2(float a, float b) {
    __half x = __float2half(a), y = __float2half(b);
    return (uint32_t)__half_as_ushort(x) | ((uint32_t)__half_as_ushort(y) << 16);
}

// ---------------- init ----------------
__global__ void init_kernel(const float* __restrict__ hidden) {
    int i = blockIdx.x * blockDim.x + threadIdx.x;
    if (i == 0) g_bar_count = 0u;
    if (i < GRID_RNN * 32) g_rel[i] = 0u;
    if (i < BH) {
        g_a[i] = __float2half(tanhf(hidden[i]));
    }
}

// ------- pre (tensor cores): c = alpha*(x@Win^T + b_in + b_hh) + 0.025*noise
// CTA tile 128 x 64, K=128 in 2 chunks of 64. A=x fp16 single; W split hi/lo.
__global__ void __launch_bounds__(256, 1) pre_tc_kernel(
    const float* __restrict__ x, const float* __restrict__ noise,
    const float* __restrict__ w_in, const float* __restrict__ b_in,
    const float* __restrict__ b_hh)
{
    extern __shared__ char sm[];
    const int tid = threadIdx.x;
    const int c0 = blockIdx.x * 64;
    const int r0 = blockIdx.y * 128;
    const int wid = tid >> 5, lane = tid & 31;
    const int wm = (wid & 3) * 32;
    const int wn = (wid >> 2) * 32;
    const int gq = lane >> 2, q = lane & 3;

    float acc[2][4][4] = {};

    const char* pA  = sm + P_A  + (wm + gq) * PITCH + q * 4;
    const char* pBh = sm + P_BH + (wn + gq) * PITCH + q * 4;
    const char* pBl = sm + P_BL + (wn + gq) * PITCH + q * 4;

    #pragma unroll
    for (int ch = 0; ch < 2; ch++) {
        const int kc = ch * 64;
        __syncthreads();
        // A chunk: 128 rows x 64 cols fp32 -> fp16
        #pragma unroll
        for (int i = 0; i < 8; i++) {
            int idx = i * 256 + tid;
            int r = idx >> 4, c4 = idx & 15;
            int rr = r0 + r;
            const float* src = x + ((size_t)(rr & 127) * T_LEN + (rr >> 7)) * NIN + kc + c4 * 4;
            float4 v = __ldcg((const float4*)src);
            *(uint2*)(sm + P_A + r * PITCH + c4 * 8) =
                make_uint2(pack_h2(v.x, v.y), pack_h2(v.z, v.w));
        }
        // B chunk: w_in rows, fp32 -> fp16 hi/lo
        #pragma unroll
        for (int i = 0; i < 4; i++) {
            int idx = i * 256 + tid;
            int r = idx >> 4, c4 = idx & 15;
            float4 v = __ldcg((const float4*)(w_in + (size_t)(c0 + r) * NIN + kc + c4 * 4));
            float hx = __half2float(__float2half(v.x));
            float hy = __half2float(__float2half(v.y));
            float hz = __half2float(__float2half(v.z));
            float hw = __half2float(__float2half(v.w));
            *(uint2*)(sm + P_BH + r * PITCH + c4 * 8) =
                make_uint2(pack_h2(v.x, v.y), pack_h2(v.z, v.w));
            *(uint2*)(sm + P_BL + r * PITCH + c4 * 8) =
                make_uint2(pack_h2(v.x - hx, v.y - hy), pack_h2(v.z - hz, v.w - hw));
        }
        __syncthreads();

        #pragma unroll
        for (int kk = 0; kk < 4; kk++) {
            const int kb = kk * 32;
            uint32_t ah[2][4], bhf[4][2], blf[4][2];
            #pragma unroll
            for (int mt = 0; mt < 2; mt++) {
                const int mo = mt * 16 * PITCH;
                ah[mt][0] = *(const uint32_t*)(pA + mo + kb);
                ah[mt][1] = *(const uint32_t*)(pA + mo + 8 * PITCH + kb);
                ah[mt][2] = *(const uint32_t*)(pA + mo + kb + 16);
                ah[mt][3] = *(const uint32_t*)(pA + mo + 8 * PITCH + kb + 16);
            }
            #pragma unroll
            for (int j = 0; j < 4; j++) {
                bhf[j][0] = *(const uint32_t*)(pBh + j * 8 * PITCH + kb);
                bhf[j][1] = *(const uint32_t*)(pBh + j * 8 * PITCH + kb + 16);
                blf[j][0] = *(const uint32_t*)(pBl + j * 8 * PITCH + kb);
                blf[j][1] = *(const uint32_t*)(pBl + j * 8 * PITCH + kb + 16);
            }
            #pragma unroll
            for (int mt = 0; mt < 2; mt++)
                #pragma unroll
                for (int j = 0; j < 4; j++) {
                    mma_f16(acc[mt][j][0], acc[mt][j][1], acc[mt][j][2], acc[mt][j][3],
                            ah[mt][0], ah[mt][1], ah[mt][2], ah[mt][3], bhf[j][0], bhf[j][1]);
                    mma_f16(acc[mt][j][0], acc[mt][j][1], acc[mt][j][2], acc[mt][j][3],
                            ah[mt][0], ah[mt][1], ah[mt][2], ah[mt][3], blf[j][0], blf[j][1]);
                }
        }
    }

    #pragma unroll
    for (int j = 0; j < 4; j++) {
        int col = c0 + wn + j * 8 + q * 2;
        float bi0 = b_in[col] + b_hh[col];
        float bi1 = b_in[col + 1] + b_hh[col + 1];
        #pragma unroll
        for (int mt = 0; mt < 2; mt++) {
            int row = r0 + wm + mt * 16 + gq;
            float2 n0 = __ldcg((const float2*)(noise + (size_t)row * H_SZ + col));
            float2 n1 = __ldcg((const float2*)(noise + (size_t)(row + 8) * H_SZ + col));
            float2 v0, v1;
            v0.x = ALPHA_F * (acc[mt][j][0] + bi0) + NSCALE * n0.x;
            v0.y = ALPHA_F * (acc[mt][j][1] + bi1) + NSCALE * n0.y;
            v1.x = ALPHA_F * (acc[mt][j][2] + bi0) + NSCALE * n1.x;
            v1.y = ALPHA_F * (acc[mt][j][3] + bi1) + NSCALE * n1.y;
            *(float2*)(g_c + (size_t)row * H_SZ + col) = v0;
            *(float2*)(g_c + (size_t)(row + 8) * H_SZ + col) = v1;
        }
    }
}

// ---- grid barrier: atomic arrival + per-CTA-line release (proven) ----------
__device__ __forceinline__ void grid_bar(int cta, unsigned epoch, unsigned* smflag) {
    __syncthreads();
    if (threadIdx.x == 0) {
        __threadfence();
        unsigned arrived = atomicAdd(&g_bar_count, 1u) + 1u;
        *smflag = (arrived == epoch * (unsigned)GRID_RNN) ? 1u : 0u;
    }
    __syncthreads();
    if (*smflag) {
        if (threadIdx.x < GRID_RNN) {
            *(volatile unsigned*)&g_rel[threadIdx.x * 32] = epoch;
        }
    } else if (threadIdx.x == 0) {
        while (*(volatile unsigned*)&g_rel[cta * 32] < epoch) { }
        __threadfence();
    }
    __syncthreads();
}

// ---------------- persistent recurrent kernel (R11 structure, fp16 2-product)
// 128 CTAs = 4 k-splits x 2 b-tiles x 16 h-tiles. 256 threads, 8 warps 16x32.
__global__ void __launch_bounds__(256, 1) rnn_kernel(
    float* __restrict__ hid_list, float* __restrict__ h_final,
    const float* __restrict__ w_hh, const float* __restrict__ hidden0)
{
    extern __shared__ char sm[];
    __shared__ unsigned smflag;
    const int cta = blockIdx.x;
    const int ks = cta & 3;
    const int bt = (cta >> 2) & 1;
    const int ht = cta >> 3;
    const int tid = threadIdx.x;
    const int r0 = bt * 64, c0 = ht * 64, k0 = ks * 256;

    // resident weight slice -> fp16 hi/lo (once)
    for (int e = tid; e < 64 * 256; e += 256) {
        int n = e >> 8, k = e & 255;
        float w = w_hh[(size_t)(c0 + n) * H_SZ + k0 + k];
        __half wh = __float2half(w);
        __half wl = __float2half(w - __half2float(wh));
        *(__half*)(sm + B_HI + n * PITCH + k * 2) = wh;
        *(__half*)(sm + B_LO + n * PITCH + k * 2) = wl;
    }
    __syncthreads();

    const int wid = tid >> 5, lane = tid & 31;
    const int wm = (wid & 3) * 16;
    const int wn = (wid >> 2) * 32;
    const int gq = lane >> 2;
    const int q  = lane & 3;

    float* pout = g_p + (size_t)ks * BH;
    const char* pA  = sm + A_SM + (wm + gq) * PITCH + q * 4;
    const char* pBh = sm + B_HI + (wn + gq) * PITCH + q * 4;
    const char* pBl = sm + B_LO + (wn + gq) * PITCH + q * 4;

    const int e  = cta * 1024 + tid * 4;
    const int eb = e >> 10, eh = e & 1023;

    float4 hreg = *(const float4*)(hidden0 + e);
    unsigned epoch = 0;

    for (int t = 0; t < T_LEN; t++) {
        float4 cv = __ldcg((const float4*)(g_c + (size_t)t * BH + e));

        // stage A slice: 64 rows x 256 fp16 = 32KB (single buffer)
        #pragma unroll
        for (int i = 0; i < 4; i++) {
            int idx = i * 256 + tid;              // 0..1023 uint4 units
            int r = idx >> 4, cc = idx & 15;      // r 0..63, cc 0..15 (x32B? no: x16B over 256B span)
            size_t goff = (size_t)(r0 + r) * 2048 + (size_t)k0 * 2 + cc * 32;
            uint4 v0 = __ldcg((const uint4*)((const char*)g_a + goff));
            uint4 v1 = __ldcg((const uint4*)((const char*)g_a + goff + 16));
            *(uint4*)(sm + A_SM + r * PITCH + cc * 32) = v0;
            *(uint4*)(sm + A_SM + r * PITCH + cc * 32 + 16) = v1;
        }
        __syncthreads();

        // fp16 2-product GEMM: acc = A*Bhi + A*Blo
        float acc[4][4] = {};
        #pragma unroll
        for (int kk = 0; kk < 16; kk++) {
            const int kb = kk * 32;
            uint32_t a0 = *(const uint32_t*)(pA + kb);
            uint32_t a1 = *(const uint32_t*)(pA + 8 * PITCH + kb);
            uint32_t a2 = *(const uint32_t*)(pA + kb + 16);
            uint32_t a3 = *(const uint32_t*)(pA + 8 * PITCH + kb + 16);
            #pragma unroll
            for (int j = 0; j < 4; j++) {
                uint32_t bh0 = *(const uint32_t*)(pBh + j * 8 * PITCH + kb);
                uint32_t bh1 = *(const uint32_t*)(pBh + j * 8 * PITCH + kb + 16);
                uint32_t bl0 = *(const uint32_t*)(pBl + j * 8 * PITCH + kb);
                uint32_t bl1 = *(const uint32_t*)(pBl + j * 8 * PITCH + kb + 16);
                mma_f16(acc[j][0], acc[j][1], acc[j][2], acc[j][3],
                        a0, a1, a2, a3, bh0, bh1);
                mma_f16(acc[j][0], acc[j][1], acc[j][2], acc[j][3],
                        a0, a1, a2, a3, bl0, bl1);
            }
        }
        #pragma unroll
        for (int j = 0; j < 4; j++) {
            float* pp = pout + (size_t)(r0 + wm + gq) * H_SZ + c0 + wn + j * 8 + q * 2;
            *(float2*)pp = make_float2(acc[j][0], acc[j][1]);
            *(float2*)(pp + 8 * H_SZ) = make_float2(acc[j][2], acc[j][3]);
        }

        grid_bar(cta, ++epoch, &smflag);

        {
            float4 p0 = *(const float4*)(g_p + e);
            float4 p1 = *(const float4*)(g_p + 1 * BH + e);
            float4 p2 = *(const float4*)(g_p + 2 * BH + e);
            float4 p3 = *(const float4*)(g_p + 3 * BH + e);
            float4 hn;
            hn.x = LEAK_F * hreg.x + ALPHA_F * (p0.x + p1.x + p2.x + p3.x) + cv.x;
            hn.y = LEAK_F * hreg.y + ALPHA_F * (p0.y + p1.y + p2.y + p3.y) + cv.y;
            hn.z = LEAK_F * hreg.z + ALPHA_F * (p0.z + p1.z + p2.z + p3.z) + cv.z;
            hn.w = LEAK_F * hreg.w + ALPHA_F * (p0.w + p1.w + p2.w + p3.w) + cv.w;
            hreg = hn;
            *(float4*)(hid_list + ((size_t)eb * T_LEN + t) * H_SZ + eh) = hn;
            if (t == T_LEN - 1) *(float4*)(h_final + e) = hn;

            float t0 = tanhf(hn.x), t1 = tanhf(hn.y), t2 = tanhf(hn.z), t3 = tanhf(hn.w);
            uint2 hw;
            hw.x = pack_h2(t0, t1);
            hw.y = pack_h2(t2, t3);
            *(uint2*)((char*)g_a + (size_t)e * 2) = hw;
        }

        grid_bar(cta, ++epoch, &smflag);
    }
}

// ------- post (tensor cores, fp16 2-product): out = clip(hid@Wout^T + b) ----
__global__ void __launch_bounds__(256, 1) post_tc_kernel(
    const float* __restrict__ hid_list, const float* __restrict__ w_out,
    const float* __restrict__ b_out, float* __restrict__ out_list)
{
    extern __shared__ char sm[];
    const int tid = threadIdx.x;
    const int c0 = blockIdx.x * 64;
    const int r0 = blockIdx.y * 128;
    const int wid = tid >> 5, lane = tid & 31;
    const int wm = (wid & 3) * 32;
    const int wn = (wid >> 2) * 32;
    const int gq = lane >> 2, q = lane & 3;

    float acc[2][4][4] = {};

    const char* pA  = sm + P_A  + (wm + gq) * PITCH + q * 4;
    const char* pBh = sm + P_BH + (wn + gq) * PITCH + q * 4;
    const char* pBl = sm + P_BL + (wn + gq) * PITCH + q * 4;

    for (int ch = 0; ch < 16; ch++) {
        const int kc = ch * 64;
        __syncthreads();
        #pragma unroll
        for (int i = 0; i < 8; i++) {
            int idx = i * 256 + tid;
            int r = idx >> 4, c4 = idx & 15;
            float4 v = __ldcg((const float4*)(hid_list + (size_t)(r0 + r) * H_SZ + kc + c4 * 4));
            *(uint2*)(sm + P_A + r * PITCH + c4 * 8) =
                make_uint2(pack_h2(v.x, v.y), pack_h2(v.z, v.w));
        }
        #pragma unroll
        for (int i = 0; i < 4; i++) {
            int idx = i * 256 + tid;
            int r = idx >> 4, c4 = idx & 15;
            float4 v = __ldcg((const float4*)(w_out + (size_t)(c0 + r) * H_SZ + kc + c4 * 4));
            float hx = __half2float(__float2half(v.x));
            float hy = __half2float(__float2half(v.y));
            float hz = __half2float(__float2half(v.z));
            float hw = __half2float(__float2half(v.w));
            *(uint2*)(sm + P_BH + r * PITCH + c4 * 8) =
                make_uint2(pack_h2(v.x, v.y), pack_h2(v.z, v.w));
            *(uint2*)(sm + P_BL + r * PITCH + c4 * 8) =
                make_uint2(pack_h2(v.x - hx, v.y - hy), pack_h2(v.z - hz, v.w - hw));
        }
        __syncthreads();

        #pragma unroll
        for (int kk = 0; kk < 4; kk++) {
            const int kb = kk * 32;
            uint32_t ah[2][4], bhf[4][2], blf[4][2];
            #pragma unroll
            for (int mt = 0; mt < 2; mt++) {
                const int mo = mt * 16 * PITCH;
                ah[mt][0] = *(const uint32_t*)(pA + mo + kb);
                ah[mt][1] = *(const uint32_t*)(pA + mo + 8 * PITCH + kb);
                ah[mt][2] = *(const uint32_t*)(pA + mo + kb + 16);
                ah[mt][3] = *(const uint32_t*)(pA + mo + 8 * PITCH + kb + 16);
            }
            #pragma unroll
            for (int j = 0; j < 4; j++) {
                bhf[j][0] = *(const uint32_t*)(pBh + j * 8 * PITCH + kb);
                bhf[j][1] = *(const uint32_t*)(pBh + j * 8 * PITCH + kb + 16);
                blf[j][0] = *(const uint32_t*)(pBl + j * 8 * PITCH + kb);
                blf[j][1] = *(const uint32_t*)(pBl + j * 8 * PITCH + kb + 16);
            }
            #pragma unroll
            for (int mt = 0; mt < 2; mt++)
                #pragma unroll
                for (int j = 0; j < 4; j++) {
                    mma_f16(acc[mt][j][0], acc[mt][j][1], acc[mt][j][2], acc[mt][j][3],
                            ah[mt][0], ah[mt][1], ah[mt][2], ah[mt][3], bhf[j][0], bhf[j][1]);
                    mma_f16(acc[mt][j][0], acc[mt][j][1], acc[mt][j][2], acc[mt][j][3],
                            ah[mt][0], ah[mt][1], ah[mt][2], ah[mt][3], blf[j][0], blf[j][1]);
                }
        }
    }

    #pragma unroll
    for (int mt = 0; mt < 2; mt++) {
        #pragma unroll
        for (int j = 0; j < 4; j++) {
            int col = c0 + wn + j * 8 + q * 2;
            float b0 = b_out[col], b1 = b_out[col + 1];
            int row = r0 + wm + mt * 16 + gq;
            float2 v0, v1;
            v0.x = fminf(fmaxf(acc[mt][j][0] + b0, -20.0f), 20.0f);
            v0.y = fminf(fmaxf(acc[mt][j][1] + b1, -20.0f), 20.0f);
            v1.x = fminf(fmaxf(acc[mt][j][2] + b0, -20.0f), 20.0f);
            v1.y = fminf(fmaxf(acc[mt][j][3] + b1, -20.0f), 20.0f);
            *(float2*)(out_list + (size_t)row * NOUT + col) = v0;
            *(float2*)(out_list + (size_t)(row + 8) * NOUT + col) = v1;
        }
    }
}

extern "C" void kernel_launch(void* const* d_in, const int* in_sizes, int n_in,
                              void* d_out, int out_size) {
    const float* x       = (const float*)d_in[0];
    const float* hidden0 = (const float*)d_in[1];
    const float* noise   = (const float*)d_in[2];
    const float* w_in_w  = (const float*)d_in[3];
    const float* w_in_b  = (const float*)d_in[4];
    const float* w_hh_w  = (const float*)d_in[5];
    const float* w_hh_b  = (const float*)d_in[6];
    const float* w_out_w = (const float*)d_in[7];
    const float* w_out_b = (const float*)d_in[8];

    float* out      = (float*)d_out;
    float* hid_list = out;
    float* out_list = out + (size_t)B_SZ * T_LEN * H_SZ;
    float* h_final  = out_list + (size_t)B_SZ * T_LEN * NOUT;

    cudaFuncSetAttribute(rnn_kernel, cudaFuncAttributeMaxDynamicSharedMemorySize, SM_ALLOC);
    cudaFuncSetAttribute(pre_tc_kernel, cudaFuncAttributeMaxDynamicSharedMemorySize, P_SMEM);
    cudaFuncSetAttribute(post_tc_kernel, cudaFuncAttributeMaxDynamicSharedMemorySize, P_SMEM);
    init_kernel<<<(BH + 255) / 256, 256>>>(hidden0);
    pre_tc_kernel<<<dim3(H_SZ / 64, (T_LEN * B_SZ) / 128), 256, P_SMEM>>>(
        x, noise, w_in_w, w_in_b, w_hh_b);
    rnn_kernel<<<GRID_RNN, 256, SM_ALLOC>>>(hid_list, h_final, w_hh_w, hidden0);
    post_tc_kernel<<<dim3(NOUT / 64, (B_SZ * T_LEN) / 128), 256, P_SMEM>>>(
        hid_list, w_out_w, w_out_b, out_list);
}